// round 12
// baseline (speedup 1.0000x reference)
#include <cuda_runtime.h>
#include <cuda_fp16.h>
#include <math.h>
#include <float.h>
#include <stdint.h>

#define BB 2
#define LL 4096
#define DD 768
#define HH 12
#define DH 64
#define QKV_N (3*DD)
#define MM (BB*LL)

// Scratch (no cudaMalloc allowed)
__device__ __half g_xh[(size_t)MM * DD];
__device__ __half g_wqkvt[(size_t)QKV_N * DD];  // Wqkv^T, [N][K]
__device__ __half g_wot[(size_t)DD * DD];       // Wo^T
__device__ __half g_qkvh[(size_t)MM * QKV_N];   // q pre-scaled by 0.125*log2(e)
__device__ __half g_yh[(size_t)MM * DD];

// ---------------------------------------------------------------------------
// helpers
// ---------------------------------------------------------------------------
__device__ __forceinline__ uint32_t smem_u32(const void* p) {
    uint32_t a;
    asm("{ .reg .u64 t; cvta.to.shared.u64 t, %1; cvt.u32.u64 %0, t; }"
        : "=r"(a) : "l"(p));
    return a;
}
__device__ __forceinline__ void cp16(uint32_t dst, const void* src) {
    asm volatile("cp.async.cg.shared.global [%0], [%1], 16;"
                 :: "r"(dst), "l"(src));
}
#define CP_COMMIT asm volatile("cp.async.commit_group;" ::: "memory")
#define CP_WAIT0  asm volatile("cp.async.wait_group 0;" ::: "memory")

__device__ __forceinline__ void ldsm4(uint32_t* r, uint32_t a) {
    asm volatile("ldmatrix.sync.aligned.m8n8.x4.shared.b16 {%0,%1,%2,%3}, [%4];"
        : "=r"(r[0]), "=r"(r[1]), "=r"(r[2]), "=r"(r[3]) : "r"(a));
}
__device__ __forceinline__ void ldsm4t(uint32_t* r, uint32_t a) {
    asm volatile("ldmatrix.sync.aligned.m8n8.x4.trans.shared.b16 {%0,%1,%2,%3}, [%4];"
        : "=r"(r[0]), "=r"(r[1]), "=r"(r[2]), "=r"(r[3]) : "r"(a));
}
__device__ __forceinline__ void mma16(float* d, const uint32_t* a,
                                      uint32_t b0, uint32_t b1) {
    asm volatile(
        "mma.sync.aligned.m16n8k16.row.col.f32.f16.f16.f32 "
        "{%0,%1,%2,%3}, {%4,%5,%6,%7}, {%8,%9}, {%0,%1,%2,%3};"
        : "+f"(d[0]), "+f"(d[1]), "+f"(d[2]), "+f"(d[3])
        : "r"(a[0]), "r"(a[1]), "r"(a[2]), "r"(a[3]), "r"(b0), "r"(b1));
}
__device__ __forceinline__ uint32_t pack2(float a, float b) {
    __half2 h = __floats2half2_rn(a, b);
    return *reinterpret_cast<uint32_t*>(&h);
}

// ---------------------------------------------------------------------------
// merged prep kernel (unchanged from R11)
// ---------------------------------------------------------------------------
#define NCVT (MM * DD / 4 / 256)
#define NTRQ ((QKV_N / 32) * (DD / 32))
#define NTRW ((DD / 32) * (DD / 32))
#define NPREP (NCVT + NTRQ + NTRW)

__device__ __forceinline__ void tr_body(
    const float* __restrict__ in, __half* __restrict__ out,
    int R, int C, int bx, int by, float* tile)
{
    const int tx = threadIdx.x & 31, ty = threadIdx.x >> 5;
    const int c0 = bx * 32, r0 = by * 32;
    for (int j = ty; j < 32; j += 8)
        tile[j * 33 + tx] = in[(size_t)(r0 + j) * C + c0 + tx];
    __syncthreads();
    for (int j = ty; j < 32; j += 8)
        out[(size_t)(c0 + j) * R + r0 + tx] = __float2half_rn(tile[tx * 33 + j]);
}

__global__ __launch_bounds__(256) void prep(
    const float* __restrict__ x, __half* __restrict__ xh,
    const float* __restrict__ Wqkv, __half* __restrict__ wqkvt,
    const float* __restrict__ Wo, __half* __restrict__ wot)
{
    __shared__ float tile[32 * 33];
    const int bid = blockIdx.x;
    if (bid < NCVT) {
        const int i = bid * 256 + threadIdx.x;
        float4 v = ((const float4*)x)[i];
        uint2 u;
        u.x = pack2(v.x, v.y);
        u.y = pack2(v.z, v.w);
        ((uint2*)xh)[i] = u;
    } else if (bid < NCVT + NTRQ) {
        const int tb = bid - NCVT;
        tr_body(Wqkv, wqkvt, DD, QKV_N, tb % (QKV_N / 32), tb / (QKV_N / 32), tile);
    } else {
        const int tb = bid - NCVT - NTRQ;
        tr_body(Wo, wot, DD, DD, tb % (DD / 32), tb / (DD / 32), tile);
    }
}

// ---------------------------------------------------------------------------
// fp16 GEMM, templated on BN (128: 2x4 warps, warp 64x32; 64: 4x2, warp 32x32)
// ---------------------------------------------------------------------------
#define GROW 144
#define QSCALE 0.1803368801111204f   // 0.125 * log2(e)

template<int BN>
__device__ __forceinline__ void g_stage(
    const __half* __restrict__ A, const __half* __restrict__ Bt,
    uint32_t as, uint32_t bs, int m0, int n0, int k0, int K, int tid)
{
    const int r = tid >> 3, c = tid & 7;
    const __half* Ap = A + (size_t)(m0 + r) * K + k0 + c * 8;
    const __half* Bp = Bt + (size_t)(n0 + r) * K + k0 + c * 8;
    #pragma unroll
    for (int p = 0; p < 4; p++)
        cp16(as + (r + p * 32) * GROW + c * 16, Ap + (size_t)(p * 32) * K);
    #pragma unroll
    for (int p = 0; p < BN / 32; p++)
        cp16(bs + (r + p * 32) * GROW + c * 16, Bp + (size_t)(p * 32) * K);
}

template<int OUTH, int BN>
__global__ __launch_bounds__(256) void gemm_h(
    const __half* __restrict__ A, const __half* __restrict__ Bt,
    const float* __restrict__ bias, void* __restrict__ Cout,
    int M, int N, int K)
{
    constexpr int NWN = BN / 32;        // warps along N
    constexpr int WMT = 128 / (8 / NWN);// warp m-tile: 64 (BN=128) / 32 (BN=64)
    constexpr int MI  = WMT / 16;       // 4 or 2
    constexpr int GSTb = (128 + BN) * GROW;

    extern __shared__ char sm[];
    const uint32_t sbase = smem_u32(sm);
    const int tid = threadIdx.x, warp = tid >> 5, lane = tid & 31;
    const int g = lane >> 2, t = lane & 3;
    const int wm = (warp / NWN) * WMT, wn = (warp % NWN) * 32;
    const int m0 = blockIdx.y * 128, n0 = blockIdx.x * BN;

    float acc[MI][4][4] = {};

    g_stage<BN>(A, Bt, sbase, sbase + 128 * GROW, m0, n0, 0, K, tid);
    CP_COMMIT;

    const int NCH = K / 64;
    for (int ch = 0; ch < NCH; ch++) {
        CP_WAIT0;
        __syncthreads();
        if (ch + 1 < NCH) {
            const uint32_t s = sbase + ((ch + 1) & 1) * GSTb;
            g_stage<BN>(A, Bt, s, s + 128 * GROW, m0, n0, (ch + 1) * 64, K, tid);
            CP_COMMIT;
        }
        const uint32_t as = sbase + (ch & 1) * GSTb;
        const uint32_t bs = as + 128 * GROW;
        #pragma unroll
        for (int j = 0; j < 4; j++) {
            const int kk = j * 16;
            uint32_t af[MI][4];
            #pragma unroll
            for (int mi = 0; mi < MI; mi++)
                ldsm4(af[mi], as + (wm + mi * 16 + (lane & 15)) * GROW
                              + (kk + ((lane >> 4) << 3)) * 2);
            #pragma unroll
            for (int np = 0; np < 2; np++) {
                uint32_t bf[4];
                ldsm4(bf, bs + (wn + np * 16 + (lane & 7) + ((lane >> 4) << 3)) * GROW
                          + (kk + (((lane >> 3) & 1) << 3)) * 2);
                #pragma unroll
                for (int mi = 0; mi < MI; mi++) {
                    mma16(acc[mi][np * 2],     af[mi], bf[0], bf[1]);
                    mma16(acc[mi][np * 2 + 1], af[mi], bf[2], bf[3]);
                }
            }
        }
        __syncthreads();
    }

    #pragma unroll
    for (int mi = 0; mi < MI; mi++) {
        const int row = m0 + wm + mi * 16 + g;
        #pragma unroll
        for (int nb = 0; nb < 4; nb++) {
            const int col = n0 + wn + nb * 8 + 2 * t;
            const float b0 = bias[col], b1 = bias[col + 1];
            if (OUTH) {
                const float sc = (col < DD) ? QSCALE : 1.0f;
                __half* C = (__half*)Cout;
                *(uint32_t*)(C + (size_t)row * N + col) =
                    pack2((acc[mi][nb][0] + b0) * sc, (acc[mi][nb][1] + b1) * sc);
                *(uint32_t*)(C + (size_t)(row + 8) * N + col) =
                    pack2((acc[mi][nb][2] + b0) * sc, (acc[mi][nb][3] + b1) * sc);
            } else {
                float* C = (float*)Cout;
                *(float2*)(C + (size_t)row * N + col) =
                    make_float2(acc[mi][nb][0] + b0, acc[mi][nb][1] + b1);
                *(float2*)(C + (size_t)(row + 8) * N + col) =
                    make_float2(acc[mi][nb][2] + b0, acc[mi][nb][3] + b1);
            }
        }
    }
}

// ---------------------------------------------------------------------------
// fp16 causal flash attention (R9 body: fixed-max exp2 softmax). Unchanged.
// ---------------------------------------------------------------------------
#define FROW 144
#define FST  18432
#define FDSM (2*FST)

__global__ __launch_bounds__(256) void flash_h(
    const __half* __restrict__ qkv, __half* __restrict__ y)
{
    extern __shared__ char sm[];
    const uint32_t sbase = smem_u32(sm);
    const int tid = threadIdx.x, warp = tid >> 5, lane = tid & 31;
    const int g = lane >> 2, t = lane & 3;
    const int qt = (int)gridDim.x - 1 - (int)blockIdx.x;
    const int h = blockIdx.y, b = blockIdx.z;
    const int qbase = qt * 128, wrow = warp * 16;

    const __half* __restrict__ Qg = qkv + (size_t)b * LL * QKV_N + h * DH;
    const __half* __restrict__ Kg = qkv + (size_t)b * LL * QKV_N + DD + h * DH;
    const __half* __restrict__ Vg = qkv + (size_t)b * LL * QKV_N + 2 * DD + h * DH;

    #pragma unroll
    for (int p = 0; p < 4; p++) {
        const int id = p * 256 + tid;
        const int r = id >> 3, c = id & 7;
        cp16(sbase + r * FROW + c * 16, Qg + (size_t)(qbase + r) * QKV_N + c * 8);
    }
    CP_COMMIT; CP_WAIT0;
    __syncthreads();
    uint32_t qf[4][4];
    #pragma unroll
    for (int j = 0; j < 4; j++)
        ldsm4(qf[j], sbase + (wrow + (lane & 15)) * FROW
                     + (j * 16 + ((lane >> 4) << 3)) * 2);
    __syncthreads();

    float o[8][4] = {};
    float l_lo = 0.f, l_hi = 0.f;
    const int ktmax = 2 * (qt + 1);

    #pragma unroll
    for (int p = 0; p < 2; p++) {
        const int id = p * 256 + tid;
        const int r = id >> 3, c = id & 7;
        cp16(sbase + r * FROW + c * 16, Kg + (size_t)r * QKV_N + c * 8);
        cp16(sbase + 9216 + r * FROW + c * 16, Vg + (size_t)r * QKV_N + c * 8);
    }
    CP_COMMIT;

    for (int kt = 0; kt < ktmax; kt++) {
        CP_WAIT0;
        __syncthreads();
        if (kt + 1 < ktmax) {
            const uint32_t s = sbase + ((kt + 1) & 1) * FST;
            const int nb = (kt + 1) * 64;
            #pragma unroll
            for (int p = 0; p < 2; p++) {
                const int id = p * 256 + tid;
                const int r = id >> 3, c = id & 7;
                cp16(s + r * FROW + c * 16, Kg + (size_t)(nb + r) * QKV_N + c * 8);
                cp16(s + 9216 + r * FROW + c * 16, Vg + (size_t)(nb + r) * QKV_N + c * 8);
            }
            CP_COMMIT;
        }
        const int kbase = kt * 64;
        if (kbase <= qbase + wrow + 15) {
            const uint32_t ks = sbase + (kt & 1) * FST;
            const uint32_t vs = ks + 9216;

            float s[8][4] = {};
            #pragma unroll
            for (int j = 0; j < 4; j++) {
                const int kk = j * 16;
                #pragma unroll
                for (int np = 0; np < 4; np++) {
                    uint32_t bf[4];
                    ldsm4(bf, ks + (np * 16 + (lane & 7) + ((lane >> 4) << 3)) * FROW
                              + (kk + (((lane >> 3) & 1) << 3)) * 2);
                    mma16(s[np * 2],     qf[j], bf[0], bf[1]);
                    mma16(s[np * 2 + 1], qf[j], bf[2], bf[3]);
                }
            }

            if (kbase + 63 > qbase + wrow) {
                const int row_lo = qbase + wrow + g, row_hi = row_lo + 8;
                #pragma unroll
                for (int n = 0; n < 8; n++) {
                    const int c0 = kbase + n * 8 + 2 * t;
                    if (c0 > row_lo)     s[n][0] = -FLT_MAX;
                    if (c0 + 1 > row_lo) s[n][1] = -FLT_MAX;
                    if (c0 > row_hi)     s[n][2] = -FLT_MAX;
                    if (c0 + 1 > row_hi) s[n][3] = -FLT_MAX;
                }
            }

            #pragma unroll
            for (int n = 0; n < 8; n++) {
                s[n][0] = exp2f(s[n][0]);
                s[n][1] = exp2f(s[n][1]);
                s[n][2] = exp2f(s[n][2]);
                s[n][3] = exp2f(s[n][3]);
                l_lo += s[n][0] + s[n][1];
                l_hi += s[n][2] + s[n][3];
            }

            #pragma unroll
            for (int j = 0; j < 4; j++) {
                uint32_t pa[4];
                pa[0] = pack2(s[2 * j][0],     s[2 * j][1]);
                pa[1] = pack2(s[2 * j][2],     s[2 * j][3]);
                pa[2] = pack2(s[2 * j + 1][0], s[2 * j + 1][1]);
                pa[3] = pack2(s[2 * j + 1][2], s[2 * j + 1][3]);
                const int kk = j * 16;
                #pragma unroll
                for (int np = 0; np < 4; np++) {
                    uint32_t bf[4];
                    ldsm4t(bf, vs + (kk + (lane & 7) + (((lane >> 3) & 1) << 3)) * FROW
                               + (np * 16 + ((lane >> 4) << 3)) * 2);
                    mma16(o[np * 2],     pa, bf[0], bf[1]);
                    mma16(o[np * 2 + 1], pa, bf[2], bf[3]);
                }
            }
        }
    }

    l_lo += __shfl_xor_sync(0xffffffffu, l_lo, 1);
    l_lo += __shfl_xor_sync(0xffffffffu, l_lo, 2);
    l_hi += __shfl_xor_sync(0xffffffffu, l_hi, 1);
    l_hi += __shfl_xor_sync(0xffffffffu, l_hi, 2);

    const float il_lo = 1.0f / l_lo;
    const float il_hi = 1.0f / l_hi;
    const int row = qbase + wrow + g;
    #pragma unroll
    for (int n = 0; n < 8; n++) {
        const int col = h * DH + n * 8 + 2 * t;
        *(uint32_t*)(y + ((size_t)b * LL + row) * DD + col) =
            pack2(o[n][0] * il_lo, o[n][1] * il_lo);
        *(uint32_t*)(y + ((size_t)b * LL + row + 8) * DD + col) =
            pack2(o[n][2] * il_hi, o[n][3] * il_hi);
    }
}

// ---------------------------------------------------------------------------
extern "C" void kernel_launch(void* const* d_in, const int* in_sizes, int n_in,
                              void* d_out, int out_size)
{
    (void)in_sizes; (void)n_in; (void)out_size;
    const float* x    = (const float*)d_in[0];
    const float* Wqkv = (const float*)d_in[1];
    const float* bqkv = (const float*)d_in[2];
    const float* Wo   = (const float*)d_in[3];
    const float* bo   = (const float*)d_in[4];
    float* out = (float*)d_out;

    __half *xh, *wqkvt, *wot, *qkvh, *yh;
    cudaGetSymbolAddress((void**)&xh, g_xh);
    cudaGetSymbolAddress((void**)&wqkvt, g_wqkvt);
    cudaGetSymbolAddress((void**)&wot, g_wot);
    cudaGetSymbolAddress((void**)&qkvh, g_qkvh);
    cudaGetSymbolAddress((void**)&yh, g_yh);

    constexpr int GDSM1 = 2 * (128 + 128) * GROW;   // 73728
    constexpr int GDSM0 = 2 * (128 + 64) * GROW;    // 55296

    static bool attr_done = false;
    if (!attr_done) {
        cudaFuncSetAttribute((const void*)gemm_h<1, 128>,
                             cudaFuncAttributeMaxDynamicSharedMemorySize, GDSM1);
        cudaFuncSetAttribute((const void*)gemm_h<0, 64>,
                             cudaFuncAttributeMaxDynamicSharedMemorySize, GDSM0);
        cudaFuncSetAttribute((const void*)flash_h,
                             cudaFuncAttributeMaxDynamicSharedMemorySize, FDSM);
        attr_done = true;
    }

    prep<<<NPREP, 256>>>(x, xh, Wqkv, wqkvt, Wo, wot);

    gemm_h<1, 128><<<dim3(QKV_N / 128, MM / 128), 256, GDSM1>>>(
        xh, wqkvt, bqkv, qkvh, MM, QKV_N, DD);

    flash_h<<<dim3(LL / 128, HH, BB), 256, FDSM>>>(qkvh, yh);

    gemm_h<0, 64><<<dim3(DD / 64, MM / 128), 256, GDSM0>>>(
        yh, wot, bo, out, MM, DD, DD);
}

// round 13
// speedup vs baseline: 1.0054x; 1.0054x over previous
#include <cuda_runtime.h>
#include <cuda_fp16.h>
#include <math.h>
#include <float.h>
#include <stdint.h>

#define BB 2
#define LL 4096
#define DD 768
#define HH 12
#define DH 64
#define QKV_N (3*DD)
#define MM (BB*LL)

// Scratch (no cudaMalloc allowed)
__device__ __half g_xh[(size_t)MM * DD];
__device__ __half g_wqkvt[(size_t)QKV_N * DD];  // Wqkv^T, [N][K]
__device__ __half g_wot[(size_t)DD * DD];       // Wo^T
__device__ __half g_qkvh[(size_t)MM * QKV_N];   // q pre-scaled by 0.125*log2(e)
__device__ __half g_yh[(size_t)MM * DD];

// ---------------------------------------------------------------------------
// helpers
// ---------------------------------------------------------------------------
__device__ __forceinline__ uint32_t smem_u32(const void* p) {
    uint32_t a;
    asm("{ .reg .u64 t; cvta.to.shared.u64 t, %1; cvt.u32.u64 %0, t; }"
        : "=r"(a) : "l"(p));
    return a;
}
__device__ __forceinline__ void cp16(uint32_t dst, const void* src) {
    asm volatile("cp.async.cg.shared.global [%0], [%1], 16;"
                 :: "r"(dst), "l"(src));
}
#define CP_COMMIT asm volatile("cp.async.commit_group;" ::: "memory")
#define CP_WAIT0  asm volatile("cp.async.wait_group 0;" ::: "memory")

__device__ __forceinline__ void ldsm4(uint32_t* r, uint32_t a) {
    asm volatile("ldmatrix.sync.aligned.m8n8.x4.shared.b16 {%0,%1,%2,%3}, [%4];"
        : "=r"(r[0]), "=r"(r[1]), "=r"(r[2]), "=r"(r[3]) : "r"(a));
}
__device__ __forceinline__ void ldsm4t(uint32_t* r, uint32_t a) {
    asm volatile("ldmatrix.sync.aligned.m8n8.x4.trans.shared.b16 {%0,%1,%2,%3}, [%4];"
        : "=r"(r[0]), "=r"(r[1]), "=r"(r[2]), "=r"(r[3]) : "r"(a));
}
__device__ __forceinline__ void mma16(float* d, const uint32_t* a,
                                      uint32_t b0, uint32_t b1) {
    asm volatile(
        "mma.sync.aligned.m16n8k16.row.col.f32.f16.f16.f32 "
        "{%0,%1,%2,%3}, {%4,%5,%6,%7}, {%8,%9}, {%0,%1,%2,%3};"
        : "+f"(d[0]), "+f"(d[1]), "+f"(d[2]), "+f"(d[3])
        : "r"(a[0]), "r"(a[1]), "r"(a[2]), "r"(a[3]), "r"(b0), "r"(b1));
}
__device__ __forceinline__ uint32_t pack2(float a, float b) {
    __half2 h = __floats2half2_rn(a, b);
    return *reinterpret_cast<uint32_t*>(&h);
}

// ---------------------------------------------------------------------------
// merged prep kernel (unchanged from R11)
// ---------------------------------------------------------------------------
#define NCVT (MM * DD / 4 / 256)
#define NTRQ ((QKV_N / 32) * (DD / 32))
#define NTRW ((DD / 32) * (DD / 32))
#define NPREP (NCVT + NTRQ + NTRW)

__device__ __forceinline__ void tr_body(
    const float* __restrict__ in, __half* __restrict__ out,
    int R, int C, int bx, int by, float* tile)
{
    const int tx = threadIdx.x & 31, ty = threadIdx.x >> 5;
    const int c0 = bx * 32, r0 = by * 32;
    for (int j = ty; j < 32; j += 8)
        tile[j * 33 + tx] = in[(size_t)(r0 + j) * C + c0 + tx];
    __syncthreads();
    for (int j = ty; j < 32; j += 8)
        out[(size_t)(c0 + j) * R + r0 + tx] = __float2half_rn(tile[tx * 33 + j]);
}

__global__ __launch_bounds__(256) void prep(
    const float* __restrict__ x, __half* __restrict__ xh,
    const float* __restrict__ Wqkv, __half* __restrict__ wqkvt,
    const float* __restrict__ Wo, __half* __restrict__ wot)
{
    __shared__ float tile[32 * 33];
    const int bid = blockIdx.x;
    if (bid < NCVT) {
        const int i = bid * 256 + threadIdx.x;
        float4 v = ((const float4*)x)[i];
        uint2 u;
        u.x = pack2(v.x, v.y);
        u.y = pack2(v.z, v.w);
        ((uint2*)xh)[i] = u;
    } else if (bid < NCVT + NTRQ) {
        const int tb = bid - NCVT;
        tr_body(Wqkv, wqkvt, DD, QKV_N, tb % (QKV_N / 32), tb / (QKV_N / 32), tile);
    } else {
        const int tb = bid - NCVT - NTRQ;
        tr_body(Wo, wot, DD, DD, tb % (DD / 32), tb / (DD / 32), tile);
    }
}

// ---------------------------------------------------------------------------
// fp16 GEMM (R11 body, BN=128 for both uses)
// ---------------------------------------------------------------------------
#define GROW 144
#define GST  36864
#define GDSM (2*GST)
#define QSCALE 0.1803368801111204f   // 0.125 * log2(e)

__device__ __forceinline__ void g_stage(
    const __half* __restrict__ A, const __half* __restrict__ Bt,
    uint32_t as, uint32_t bs, int m0, int n0, int k0, int K, int tid)
{
    const int r = tid >> 3, c = tid & 7;
    const __half* Ap = A + (size_t)(m0 + r) * K + k0 + c * 8;
    const __half* Bp = Bt + (size_t)(n0 + r) * K + k0 + c * 8;
    #pragma unroll
    for (int p = 0; p < 4; p++) {
        cp16(as + (r + p * 32) * GROW + c * 16, Ap + (size_t)(p * 32) * K);
        cp16(bs + (r + p * 32) * GROW + c * 16, Bp + (size_t)(p * 32) * K);
    }
}

template<int OUTH>
__global__ __launch_bounds__(256) void gemm_h(
    const __half* __restrict__ A, const __half* __restrict__ Bt,
    const float* __restrict__ bias, void* __restrict__ Cout,
    int M, int N, int K)
{
    extern __shared__ char sm[];
    const uint32_t sbase = smem_u32(sm);
    const int tid = threadIdx.x, warp = tid >> 5, lane = tid & 31;
    const int g = lane >> 2, t = lane & 3;
    const int wm = (warp >> 2) * 64, wn = (warp & 3) * 32;
    const int m0 = blockIdx.y * 128, n0 = blockIdx.x * 128;

    float acc[4][4][4] = {};

    g_stage(A, Bt, sbase, sbase + 18432, m0, n0, 0, K, tid);
    CP_COMMIT;

    const int NCH = K / 64;
    for (int ch = 0; ch < NCH; ch++) {
        CP_WAIT0;
        __syncthreads();
        if (ch + 1 < NCH) {
            const uint32_t s = sbase + ((ch + 1) & 1) * GST;
            g_stage(A, Bt, s, s + 18432, m0, n0, (ch + 1) * 64, K, tid);
            CP_COMMIT;
        }
        const uint32_t as = sbase + (ch & 1) * GST;
        const uint32_t bs = as + 18432;
        #pragma unroll
        for (int j = 0; j < 4; j++) {
            const int kk = j * 16;
            uint32_t af[4][4];
            #pragma unroll
            for (int mi = 0; mi < 4; mi++)
                ldsm4(af[mi], as + (wm + mi * 16 + (lane & 15)) * GROW
                              + (kk + ((lane >> 4) << 3)) * 2);
            #pragma unroll
            for (int np = 0; np < 2; np++) {
                uint32_t bf[4];
                ldsm4(bf, bs + (wn + np * 16 + (lane & 7) + ((lane >> 4) << 3)) * GROW
                          + (kk + (((lane >> 3) & 1) << 3)) * 2);
                #pragma unroll
                for (int mi = 0; mi < 4; mi++) {
                    mma16(acc[mi][np * 2],     af[mi], bf[0], bf[1]);
                    mma16(acc[mi][np * 2 + 1], af[mi], bf[2], bf[3]);
                }
            }
        }
        __syncthreads();
    }

    #pragma unroll
    for (int mi = 0; mi < 4; mi++) {
        const int row = m0 + wm + mi * 16 + g;
        #pragma unroll
        for (int nb = 0; nb < 4; nb++) {
            const int col = n0 + wn + nb * 8 + 2 * t;
            const float b0 = bias[col], b1 = bias[col + 1];
            if (OUTH) {
                const float sc = (col < DD) ? QSCALE : 1.0f;
                __half* C = (__half*)Cout;
                *(uint32_t*)(C + (size_t)row * N + col) =
                    pack2((acc[mi][nb][0] + b0) * sc, (acc[mi][nb][1] + b1) * sc);
                *(uint32_t*)(C + (size_t)(row + 8) * N + col) =
                    pack2((acc[mi][nb][2] + b0) * sc, (acc[mi][nb][3] + b1) * sc);
            } else {
                float* C = (float*)Cout;
                *(float2*)(C + (size_t)row * N + col) =
                    make_float2(acc[mi][nb][0] + b0, acc[mi][nb][1] + b1);
                *(float2*)(C + (size_t)(row + 8) * N + col) =
                    make_float2(acc[mi][nb][2] + b0, acc[mi][nb][3] + b1);
            }
        }
    }
}

// ---------------------------------------------------------------------------
// fp16 causal flash attention, fixed-max exp2 softmax, fused per-16-col-block
// S -> mask -> exp -> pack -> PV pipeline (dependencies identical to R11;
// summation order unchanged -> bit-identical output).
// ---------------------------------------------------------------------------
#define FROW 144
#define FST  18432
#define FDSM (2*FST)

__global__ __launch_bounds__(256) void flash_h(
    const __half* __restrict__ qkv, __half* __restrict__ y)
{
    extern __shared__ char sm[];
    const uint32_t sbase = smem_u32(sm);
    const int tid = threadIdx.x, warp = tid >> 5, lane = tid & 31;
    const int g = lane >> 2, t = lane & 3;
    const int qt = (int)gridDim.x - 1 - (int)blockIdx.x;  // big tiles first
    const int h = blockIdx.y, b = blockIdx.z;
    const int qbase = qt * 128, wrow = warp * 16;

    const __half* __restrict__ Qg = qkv + (size_t)b * LL * QKV_N + h * DH;
    const __half* __restrict__ Kg = qkv + (size_t)b * LL * QKV_N + DD + h * DH;
    const __half* __restrict__ Vg = qkv + (size_t)b * LL * QKV_N + 2 * DD + h * DH;

    #pragma unroll
    for (int p = 0; p < 4; p++) {
        const int id = p * 256 + tid;
        const int r = id >> 3, c = id & 7;
        cp16(sbase + r * FROW + c * 16, Qg + (size_t)(qbase + r) * QKV_N + c * 8);
    }
    CP_COMMIT; CP_WAIT0;
    __syncthreads();
    uint32_t qf[4][4];
    #pragma unroll
    for (int j = 0; j < 4; j++)
        ldsm4(qf[j], sbase + (wrow + (lane & 15)) * FROW
                     + (j * 16 + ((lane >> 4) << 3)) * 2);
    __syncthreads();

    float o[8][4] = {};
    float l_lo = 0.f, l_hi = 0.f;
    const int ktmax = 2 * (qt + 1);

    #pragma unroll
    for (int p = 0; p < 2; p++) {
        const int id = p * 256 + tid;
        const int r = id >> 3, c = id & 7;
        cp16(sbase + r * FROW + c * 16, Kg + (size_t)r * QKV_N + c * 8);
        cp16(sbase + 9216 + r * FROW + c * 16, Vg + (size_t)r * QKV_N + c * 8);
    }
    CP_COMMIT;

    for (int kt = 0; kt < ktmax; kt++) {
        CP_WAIT0;
        __syncthreads();
        if (kt + 1 < ktmax) {
            const uint32_t s = sbase + ((kt + 1) & 1) * FST;
            const int nb = (kt + 1) * 64;
            #pragma unroll
            for (int p = 0; p < 2; p++) {
                const int id = p * 256 + tid;
                const int r = id >> 3, c = id & 7;
                cp16(s + r * FROW + c * 16, Kg + (size_t)(nb + r) * QKV_N + c * 8);
                cp16(s + 9216 + r * FROW + c * 16, Vg + (size_t)(nb + r) * QKV_N + c * 8);
            }
            CP_COMMIT;
        }
        const int kbase = kt * 64;
        if (kbase <= qbase + wrow + 15) {
            const uint32_t ks = sbase + (kt & 1) * FST;
            const uint32_t vs = ks + 9216;
            const bool diag = (kbase + 63 > qbase + wrow);
            const int row_lo = qbase + wrow + g, row_hi = row_lo + 8;

            // fused per-16-col block: S-mma -> mask -> exp2 -> pack -> PV-mma
            #pragma unroll
            for (int np = 0; np < 4; np++) {
                float s0[4] = {}, s1[4] = {};
                #pragma unroll
                for (int j = 0; j < 4; j++) {
                    const int kk = j * 16;
                    uint32_t bf[4];
                    ldsm4(bf, ks + (np * 16 + (lane & 7) + ((lane >> 4) << 3)) * FROW
                              + (kk + (((lane >> 3) & 1) << 3)) * 2);
                    mma16(s0, qf[j], bf[0], bf[1]);
                    mma16(s1, qf[j], bf[2], bf[3]);
                }

                if (diag) {
                    const int c0 = kbase + np * 16 + 2 * t;       // s0 cols
                    const int c1 = c0 + 8;                         // s1 cols
                    if (c0 > row_lo)     s0[0] = -FLT_MAX;
                    if (c0 + 1 > row_lo) s0[1] = -FLT_MAX;
                    if (c0 > row_hi)     s0[2] = -FLT_MAX;
                    if (c0 + 1 > row_hi) s0[3] = -FLT_MAX;
                    if (c1 > row_lo)     s1[0] = -FLT_MAX;
                    if (c1 + 1 > row_lo) s1[1] = -FLT_MAX;
                    if (c1 > row_hi)     s1[2] = -FLT_MAX;
                    if (c1 + 1 > row_hi) s1[3] = -FLT_MAX;
                }

                s0[0] = exp2f(s0[0]); s0[1] = exp2f(s0[1]);
                s0[2] = exp2f(s0[2]); s0[3] = exp2f(s0[3]);
                s1[0] = exp2f(s1[0]); s1[1] = exp2f(s1[1]);
                s1[2] = exp2f(s1[2]); s1[3] = exp2f(s1[3]);
                l_lo += s0[0] + s0[1];
                l_hi += s0[2] + s0[3];
                l_lo += s1[0] + s1[1];
                l_hi += s1[2] + s1[3];

                uint32_t pa[4];
                pa[0] = pack2(s0[0], s0[1]);
                pa[1] = pack2(s0[2], s0[3]);
                pa[2] = pack2(s1[0], s1[1]);
                pa[3] = pack2(s1[2], s1[3]);

                const int kk = np * 16;   // PV k-block == this column block
                #pragma unroll
                for (int nd = 0; nd < 4; nd++) {
                    uint32_t bf[4];
                    ldsm4t(bf, vs + (kk + (lane & 7) + (((lane >> 3) & 1) << 3)) * FROW
                               + (nd * 16 + ((lane >> 4) << 3)) * 2);
                    mma16(o[nd * 2],     pa, bf[0], bf[1]);
                    mma16(o[nd * 2 + 1], pa, bf[2], bf[3]);
                }
            }
        }
    }

    l_lo += __shfl_xor_sync(0xffffffffu, l_lo, 1);
    l_lo += __shfl_xor_sync(0xffffffffu, l_lo, 2);
    l_hi += __shfl_xor_sync(0xffffffffu, l_hi, 1);
    l_hi += __shfl_xor_sync(0xffffffffu, l_hi, 2);

    const float il_lo = 1.0f / l_lo;
    const float il_hi = 1.0f / l_hi;
    const int row = qbase + wrow + g;
    #pragma unroll
    for (int n = 0; n < 8; n++) {
        const int col = h * DH + n * 8 + 2 * t;
        *(uint32_t*)(y + ((size_t)b * LL + row) * DD + col) =
            pack2(o[n][0] * il_lo, o[n][1] * il_lo);
        *(uint32_t*)(y + ((size_t)b * LL + row + 8) * DD + col) =
            pack2(o[n][2] * il_hi, o[n][3] * il_hi);
    }
}

// ---------------------------------------------------------------------------
extern "C" void kernel_launch(void* const* d_in, const int* in_sizes, int n_in,
                              void* d_out, int out_size)
{
    (void)in_sizes; (void)n_in; (void)out_size;
    const float* x    = (const float*)d_in[0];
    const float* Wqkv = (const float*)d_in[1];
    const float* bqkv = (const float*)d_in[2];
    const float* Wo   = (const float*)d_in[3];
    const float* bo   = (const float*)d_in[4];
    float* out = (float*)d_out;

    __half *xh, *wqkvt, *wot, *qkvh, *yh;
    cudaGetSymbolAddress((void**)&xh, g_xh);
    cudaGetSymbolAddress((void**)&wqkvt, g_wqkvt);
    cudaGetSymbolAddress((void**)&wot, g_wot);
    cudaGetSymbolAddress((void**)&qkvh, g_qkvh);
    cudaGetSymbolAddress((void**)&yh, g_yh);

    static bool attr_done = false;
    if (!attr_done) {
        cudaFuncSetAttribute(gemm_h<1>, cudaFuncAttributeMaxDynamicSharedMemorySize, GDSM);
        cudaFuncSetAttribute(gemm_h<0>, cudaFuncAttributeMaxDynamicSharedMemorySize, GDSM);
        cudaFuncSetAttribute(flash_h, cudaFuncAttributeMaxDynamicSharedMemorySize, FDSM);
        attr_done = true;
    }

    prep<<<NPREP, 256>>>(x, xh, Wqkv, wqkvt, Wo, wot);

    gemm_h<1><<<dim3(QKV_N / 128, MM / 128), 256, GDSM>>>(
        xh, wqkvt, bqkv, qkvh, MM, QKV_N, DD);

    flash_h<<<dim3(LL / 128, HH, BB), 256, FDSM>>>(qkvh, yh);

    gemm_h<0><<<dim3(DD / 128, MM / 128), 256, GDSM>>>(
        yh, wot, bo, out, MM, DD, DD);
}

// round 14
// speedup vs baseline: 1.2127x; 1.2061x over previous
#include <cuda_runtime.h>
#include <cuda_fp16.h>
#include <math.h>
#include <float.h>
#include <stdint.h>

#define BB 2
#define LL 4096
#define DD 768
#define HH 12
#define DH 64
#define QKV_N (3*DD)
#define MM (BB*LL)

// Scratch (no cudaMalloc allowed)
__device__ __half g_xh[(size_t)MM * DD];
__device__ __half g_wqkvt[(size_t)QKV_N * DD];  // Wqkv^T, [N][K]
__device__ __half g_wot[(size_t)DD * DD];       // Wo^T
__device__ __half g_qkvh[(size_t)MM * QKV_N];   // q pre-scaled by 0.125*log2(e)
__device__ __half g_yh[(size_t)MM * DD];
__device__ int    g_cnt[64];                    // per (b,qt) head-completion count

// ---------------------------------------------------------------------------
// helpers
// ---------------------------------------------------------------------------
__device__ __forceinline__ uint32_t smem_u32(const void* p) {
    uint32_t a;
    asm("{ .reg .u64 t; cvta.to.shared.u64 t, %1; cvt.u32.u64 %0, t; }"
        : "=r"(a) : "l"(p));
    return a;
}
__device__ __forceinline__ void cp16(uint32_t dst, const void* src) {
    asm volatile("cp.async.cg.shared.global [%0], [%1], 16;"
                 :: "r"(dst), "l"(src));
}
#define CP_COMMIT asm volatile("cp.async.commit_group;" ::: "memory")
#define CP_WAIT0  asm volatile("cp.async.wait_group 0;" ::: "memory")

__device__ __forceinline__ void ldsm4(uint32_t* r, uint32_t a) {
    asm volatile("ldmatrix.sync.aligned.m8n8.x4.shared.b16 {%0,%1,%2,%3}, [%4];"
        : "=r"(r[0]), "=r"(r[1]), "=r"(r[2]), "=r"(r[3]) : "r"(a));
}
__device__ __forceinline__ void ldsm4t(uint32_t* r, uint32_t a) {
    asm volatile("ldmatrix.sync.aligned.m8n8.x4.trans.shared.b16 {%0,%1,%2,%3}, [%4];"
        : "=r"(r[0]), "=r"(r[1]), "=r"(r[2]), "=r"(r[3]) : "r"(a));
}
__device__ __forceinline__ void mma16(float* d, const uint32_t* a,
                                      uint32_t b0, uint32_t b1) {
    asm volatile(
        "mma.sync.aligned.m16n8k16.row.col.f32.f16.f16.f32 "
        "{%0,%1,%2,%3}, {%4,%5,%6,%7}, {%8,%9}, {%0,%1,%2,%3};"
        : "+f"(d[0]), "+f"(d[1]), "+f"(d[2]), "+f"(d[3])
        : "r"(a[0]), "r"(a[1]), "r"(a[2]), "r"(a[3]), "r"(b0), "r"(b1));
}
__device__ __forceinline__ uint32_t pack2(float a, float b) {
    __half2 h = __floats2half2_rn(a, b);
    return *reinterpret_cast<uint32_t*>(&h);
}

// ---------------------------------------------------------------------------
// merged prep kernel (R11) + counter reset
// ---------------------------------------------------------------------------
#define NCVT (MM * DD / 4 / 256)
#define NTRQ ((QKV_N / 32) * (DD / 32))
#define NTRW ((DD / 32) * (DD / 32))
#define NPREP (NCVT + NTRQ + NTRW)

__device__ __forceinline__ void tr_body(
    const float* __restrict__ in, __half* __restrict__ out,
    int R, int C, int bx, int by, float* tile)
{
    const int tx = threadIdx.x & 31, ty = threadIdx.x >> 5;
    const int c0 = bx * 32, r0 = by * 32;
    for (int j = ty; j < 32; j += 8)
        tile[j * 33 + tx] = in[(size_t)(r0 + j) * C + c0 + tx];
    __syncthreads();
    for (int j = ty; j < 32; j += 8)
        out[(size_t)(c0 + j) * R + r0 + tx] = __float2half_rn(tile[tx * 33 + j]);
}

__global__ __launch_bounds__(256) void prep(
    const float* __restrict__ x, __half* __restrict__ xh,
    const float* __restrict__ Wqkv, __half* __restrict__ wqkvt,
    const float* __restrict__ Wo, __half* __restrict__ wot)
{
    __shared__ float tile[32 * 33];
    const int bid = blockIdx.x;
    if (bid == 0 && threadIdx.x < 64) g_cnt[threadIdx.x] = 0;
    if (bid < NCVT) {
        const int i = bid * 256 + threadIdx.x;
        float4 v = ((const float4*)x)[i];
        uint2 u;
        u.x = pack2(v.x, v.y);
        u.y = pack2(v.z, v.w);
        ((uint2*)xh)[i] = u;
    } else if (bid < NCVT + NTRQ) {
        const int tb = bid - NCVT;
        tr_body(Wqkv, wqkvt, DD, QKV_N, tb % (QKV_N / 32), tb / (QKV_N / 32), tile);
    } else {
        const int tb = bid - NCVT - NTRQ;
        tr_body(Wo, wot, DD, DD, tb % (DD / 32), tb / (DD / 32), tile);
    }
}

// ---------------------------------------------------------------------------
// fp16 GEMM staging + QKV gemm (R11, OUTH=1 standalone)
// ---------------------------------------------------------------------------
#define GROW 144
#define GST  36864
#define GDSM (2*GST)
#define QSCALE 0.1803368801111204f   // 0.125 * log2(e)

__device__ __forceinline__ void g_stage(
    const __half* __restrict__ A, const __half* __restrict__ Bt,
    uint32_t as, uint32_t bs, int m0, int n0, int k0, int K, int tid)
{
    const int r = tid >> 3, c = tid & 7;
    const __half* Ap = A + (size_t)(m0 + r) * K + k0 + c * 8;
    const __half* Bp = Bt + (size_t)(n0 + r) * K + k0 + c * 8;
    #pragma unroll
    for (int p = 0; p < 4; p++) {
        cp16(as + (r + p * 32) * GROW + c * 16, Ap + (size_t)(p * 32) * K);
        cp16(bs + (r + p * 32) * GROW + c * 16, Bp + (size_t)(p * 32) * K);
    }
}

__global__ __launch_bounds__(256) void gemm_qkv(
    const __half* __restrict__ A, const __half* __restrict__ Bt,
    const float* __restrict__ bias, __half* __restrict__ C,
    int M, int N, int K)
{
    extern __shared__ char sm[];
    const uint32_t sbase = smem_u32(sm);
    const int tid = threadIdx.x, warp = tid >> 5, lane = tid & 31;
    const int g = lane >> 2, t = lane & 3;
    const int wm = (warp >> 2) * 64, wn = (warp & 3) * 32;
    const int m0 = blockIdx.y * 128, n0 = blockIdx.x * 128;

    float acc[4][4][4] = {};

    g_stage(A, Bt, sbase, sbase + 18432, m0, n0, 0, K, tid);
    CP_COMMIT;

    const int NCH = K / 64;
    for (int ch = 0; ch < NCH; ch++) {
        CP_WAIT0;
        __syncthreads();
        if (ch + 1 < NCH) {
            const uint32_t s = sbase + ((ch + 1) & 1) * GST;
            g_stage(A, Bt, s, s + 18432, m0, n0, (ch + 1) * 64, K, tid);
            CP_COMMIT;
        }
        const uint32_t as = sbase + (ch & 1) * GST;
        const uint32_t bs = as + 18432;
        #pragma unroll
        for (int j = 0; j < 4; j++) {
            const int kk = j * 16;
            uint32_t af[4][4];
            #pragma unroll
            for (int mi = 0; mi < 4; mi++)
                ldsm4(af[mi], as + (wm + mi * 16 + (lane & 15)) * GROW
                              + (kk + ((lane >> 4) << 3)) * 2);
            #pragma unroll
            for (int np = 0; np < 2; np++) {
                uint32_t bf[4];
                ldsm4(bf, bs + (wn + np * 16 + (lane & 7) + ((lane >> 4) << 3)) * GROW
                          + (kk + (((lane >> 3) & 1) << 3)) * 2);
                #pragma unroll
                for (int mi = 0; mi < 4; mi++) {
                    mma16(acc[mi][np * 2],     af[mi], bf[0], bf[1]);
                    mma16(acc[mi][np * 2 + 1], af[mi], bf[2], bf[3]);
                }
            }
        }
        __syncthreads();
    }

    #pragma unroll
    for (int mi = 0; mi < 4; mi++) {
        const int row = m0 + wm + mi * 16 + g;
        #pragma unroll
        for (int nb = 0; nb < 4; nb++) {
            const int col = n0 + wn + nb * 8 + 2 * t;
            const float b0 = bias[col], b1 = bias[col + 1];
            const float sc = (col < DD) ? QSCALE : 1.0f;
            *(uint32_t*)(C + (size_t)row * N + col) =
                pack2((acc[mi][nb][0] + b0) * sc, (acc[mi][nb][1] + b1) * sc);
            *(uint32_t*)(C + (size_t)(row + 8) * N + col) =
                pack2((acc[mi][nb][2] + b0) * sc, (acc[mi][nb][3] + b1) * sc);
        }
    }
}

// ---------------------------------------------------------------------------
// fused kernel: bids [0,768) = flash (R11 body, big-qt first);
//               bids [768,1152) = out-proj (R11 gemm body, fp32 out),
//               spinning on per-(b,qt) readiness counters.
// ---------------------------------------------------------------------------
#define FROW 144
#define FST  18432
#define FUSED_GRID 1152
#define FUSED_DSM GDSM   // 73728: proj needs 2*GST; flash uses first 2*FST

__global__ __launch_bounds__(256, 2) void fused(
    const __half* __restrict__ qkv, __half* __restrict__ y,
    const __half* __restrict__ wot, const float* __restrict__ bo,
    float* __restrict__ out)
{
    extern __shared__ char sm[];
    const uint32_t sbase = smem_u32(sm);
    const int tid = threadIdx.x, warp = tid >> 5, lane = tid & 31;
    const int g = lane >> 2, t = lane & 3;
    const int bid = blockIdx.x;

    if (bid < 768) {
        // ---------------- flash path ----------------
        const int qt = 31 - (bid / 24);            // big tiles first
        const int r24 = bid % 24;
        const int h = r24 % HH, b = r24 / HH;
        const int qbase = qt * 128, wrow = warp * 16;

        const __half* __restrict__ Qg = qkv + (size_t)b * LL * QKV_N + h * DH;
        const __half* __restrict__ Kg = qkv + (size_t)b * LL * QKV_N + DD + h * DH;
        const __half* __restrict__ Vg = qkv + (size_t)b * LL * QKV_N + 2 * DD + h * DH;

        #pragma unroll
        for (int p = 0; p < 4; p++) {
            const int id = p * 256 + tid;
            const int rr = id >> 3, c = id & 7;
            cp16(sbase + rr * FROW + c * 16, Qg + (size_t)(qbase + rr) * QKV_N + c * 8);
        }
        CP_COMMIT; CP_WAIT0;
        __syncthreads();
        uint32_t qf[4][4];
        #pragma unroll
        for (int j = 0; j < 4; j++)
            ldsm4(qf[j], sbase + (wrow + (lane & 15)) * FROW
                         + (j * 16 + ((lane >> 4) << 3)) * 2);
        __syncthreads();

        float o[8][4] = {};
        float l_lo = 0.f, l_hi = 0.f;
        const int ktmax = 2 * (qt + 1);

        #pragma unroll
        for (int p = 0; p < 2; p++) {
            const int id = p * 256 + tid;
            const int rr = id >> 3, c = id & 7;
            cp16(sbase + rr * FROW + c * 16, Kg + (size_t)rr * QKV_N + c * 8);
            cp16(sbase + 9216 + rr * FROW + c * 16, Vg + (size_t)rr * QKV_N + c * 8);
        }
        CP_COMMIT;

        for (int kt = 0; kt < ktmax; kt++) {
            CP_WAIT0;
            __syncthreads();
            if (kt + 1 < ktmax) {
                const uint32_t s = sbase + ((kt + 1) & 1) * FST;
                const int nb = (kt + 1) * 64;
                #pragma unroll
                for (int p = 0; p < 2; p++) {
                    const int id = p * 256 + tid;
                    const int rr = id >> 3, c = id & 7;
                    cp16(s + rr * FROW + c * 16, Kg + (size_t)(nb + rr) * QKV_N + c * 8);
                    cp16(s + 9216 + rr * FROW + c * 16, Vg + (size_t)(nb + rr) * QKV_N + c * 8);
                }
                CP_COMMIT;
            }
            const int kbase = kt * 64;
            if (kbase <= qbase + wrow + 15) {
                const uint32_t ks = sbase + (kt & 1) * FST;
                const uint32_t vs = ks + 9216;

                float s[8][4] = {};
                #pragma unroll
                for (int j = 0; j < 4; j++) {
                    const int kk = j * 16;
                    #pragma unroll
                    for (int np = 0; np < 4; np++) {
                        uint32_t bf[4];
                        ldsm4(bf, ks + (np * 16 + (lane & 7) + ((lane >> 4) << 3)) * FROW
                                  + (kk + (((lane >> 3) & 1) << 3)) * 2);
                        mma16(s[np * 2],     qf[j], bf[0], bf[1]);
                        mma16(s[np * 2 + 1], qf[j], bf[2], bf[3]);
                    }
                }

                if (kbase + 63 > qbase + wrow) {
                    const int row_lo = qbase + wrow + g, row_hi = row_lo + 8;
                    #pragma unroll
                    for (int n = 0; n < 8; n++) {
                        const int c0 = kbase + n * 8 + 2 * t;
                        if (c0 > row_lo)     s[n][0] = -FLT_MAX;
                        if (c0 + 1 > row_lo) s[n][1] = -FLT_MAX;
                        if (c0 > row_hi)     s[n][2] = -FLT_MAX;
                        if (c0 + 1 > row_hi) s[n][3] = -FLT_MAX;
                    }
                }

                #pragma unroll
                for (int n = 0; n < 8; n++) {
                    s[n][0] = exp2f(s[n][0]);
                    s[n][1] = exp2f(s[n][1]);
                    s[n][2] = exp2f(s[n][2]);
                    s[n][3] = exp2f(s[n][3]);
                    l_lo += s[n][0] + s[n][1];
                    l_hi += s[n][2] + s[n][3];
                }

                #pragma unroll
                for (int j = 0; j < 4; j++) {
                    uint32_t pa[4];
                    pa[0] = pack2(s[2 * j][0],     s[2 * j][1]);
                    pa[1] = pack2(s[2 * j][2],     s[2 * j][3]);
                    pa[2] = pack2(s[2 * j + 1][0], s[2 * j + 1][1]);
                    pa[3] = pack2(s[2 * j + 1][2], s[2 * j + 1][3]);
                    const int kk = j * 16;
                    #pragma unroll
                    for (int np = 0; np < 4; np++) {
                        uint32_t bf[4];
                        ldsm4t(bf, vs + (kk + (lane & 7) + (((lane >> 3) & 1) << 3)) * FROW
                                   + (np * 16 + ((lane >> 4) << 3)) * 2);
                        mma16(o[np * 2],     pa, bf[0], bf[1]);
                        mma16(o[np * 2 + 1], pa, bf[2], bf[3]);
                    }
                }
            }
        }

        l_lo += __shfl_xor_sync(0xffffffffu, l_lo, 1);
        l_lo += __shfl_xor_sync(0xffffffffu, l_lo, 2);
        l_hi += __shfl_xor_sync(0xffffffffu, l_hi, 1);
        l_hi += __shfl_xor_sync(0xffffffffu, l_hi, 2);

        const float il_lo = 1.0f / l_lo;
        const float il_hi = 1.0f / l_hi;
        const int row = qbase + wrow + g;
        #pragma unroll
        for (int n = 0; n < 8; n++) {
            const int col = h * DH + n * 8 + 2 * t;
            *(uint32_t*)(y + ((size_t)b * LL + row) * DD + col) =
                pack2(o[n][0] * il_lo, o[n][1] * il_lo);
            *(uint32_t*)(y + ((size_t)b * LL + row + 8) * DD + col) =
                pack2(o[n][2] * il_hi, o[n][3] * il_hi);
        }

        // publish completion of this (b, qt) slice for head h
        __threadfence();
        __syncthreads();
        if (tid == 0) atomicAdd(&g_cnt[b * 32 + qt], 1);

    } else {
        // ---------------- out-proj path ----------------
        const int pid = bid - 768;                 // 0..383
        const int qtp = 31 - (pid / 12);           // match flash readiness order
        const int r12 = pid % 12;
        const int n0 = (r12 % 6) * 128;
        const int pb = r12 / 6;
        const int yy = pb * 32 + qtp;              // row-block index (0..63)
        const int m0 = yy * 128;

        // wait until all 12 heads wrote these 128 y-rows
        if (tid == 0) {
            while (atomicAdd(&g_cnt[yy], 0) < HH) __nanosleep(200);
        }
        __syncthreads();
        __threadfence();

        const int wm = (warp >> 2) * 64, wn = (warp & 3) * 32;
        float acc[4][4][4] = {};

        g_stage(y, wot, sbase, sbase + 18432, m0, n0, 0, DD, tid);
        CP_COMMIT;

        const int NCH = DD / 64;
        for (int ch = 0; ch < NCH; ch++) {
            CP_WAIT0;
            __syncthreads();
            if (ch + 1 < NCH) {
                const uint32_t s = sbase + ((ch + 1) & 1) * GST;
                g_stage(y, wot, s, s + 18432, m0, n0, (ch + 1) * 64, DD, tid);
                CP_COMMIT;
            }
            const uint32_t as = sbase + (ch & 1) * GST;
            const uint32_t bs = as + 18432;
            #pragma unroll
            for (int j = 0; j < 4; j++) {
                const int kk = j * 16;
                uint32_t af[4][4];
                #pragma unroll
                for (int mi = 0; mi < 4; mi++)
                    ldsm4(af[mi], as + (wm + mi * 16 + (lane & 15)) * GROW
                                  + (kk + ((lane >> 4) << 3)) * 2);
                #pragma unroll
                for (int np = 0; np < 2; np++) {
                    uint32_t bf[4];
                    ldsm4(bf, bs + (wn + np * 16 + (lane & 7) + ((lane >> 4) << 3)) * GROW
                              + (kk + (((lane >> 3) & 1) << 3)) * 2);
                    #pragma unroll
                    for (int mi = 0; mi < 4; mi++) {
                        mma16(acc[mi][np * 2],     af[mi], bf[0], bf[1]);
                        mma16(acc[mi][np * 2 + 1], af[mi], bf[2], bf[3]);
                    }
                }
            }
            __syncthreads();
        }

        #pragma unroll
        for (int mi = 0; mi < 4; mi++) {
            const int row = m0 + wm + mi * 16 + g;
            #pragma unroll
            for (int nb = 0; nb < 4; nb++) {
                const int col = n0 + wn + nb * 8 + 2 * t;
                const float b0 = bo[col], b1 = bo[col + 1];
                *(float2*)(out + (size_t)row * DD + col) =
                    make_float2(acc[mi][nb][0] + b0, acc[mi][nb][1] + b1);
                *(float2*)(out + (size_t)(row + 8) * DD + col) =
                    make_float2(acc[mi][nb][2] + b0, acc[mi][nb][3] + b1);
            }
        }
    }
}

// ---------------------------------------------------------------------------
extern "C" void kernel_launch(void* const* d_in, const int* in_sizes, int n_in,
                              void* d_out, int out_size)
{
    (void)in_sizes; (void)n_in; (void)out_size;
    const float* x    = (const float*)d_in[0];
    const float* Wqkv = (const float*)d_in[1];
    const float* bqkv = (const float*)d_in[2];
    const float* Wo   = (const float*)d_in[3];
    const float* bo   = (const float*)d_in[4];
    float* out = (float*)d_out;

    __half *xh, *wqkvt, *wot, *qkvh, *yh;
    cudaGetSymbolAddress((void**)&xh, g_xh);
    cudaGetSymbolAddress((void**)&wqkvt, g_wqkvt);
    cudaGetSymbolAddress((void**)&wot, g_wot);
    cudaGetSymbolAddress((void**)&qkvh, g_qkvh);
    cudaGetSymbolAddress((void**)&yh, g_yh);

    static bool attr_done = false;
    if (!attr_done) {
        cudaFuncSetAttribute(gemm_qkv, cudaFuncAttributeMaxDynamicSharedMemorySize, GDSM);
        cudaFuncSetAttribute(fused, cudaFuncAttributeMaxDynamicSharedMemorySize, FUSED_DSM);
        attr_done = true;
    }

    prep<<<NPREP, 256>>>(x, xh, Wqkv, wqkvt, Wo, wot);

    gemm_qkv<<<dim3(QKV_N / 128, MM / 128), 256, GDSM>>>(
        xh, wqkvt, bqkv, qkvh, MM, QKV_N, DD);

    fused<<<FUSED_GRID, 256, FUSED_DSM>>>(qkvh, yh, wot, bo, out);
}